// round 15
// baseline (speedup 1.0000x reference)
#include <cuda_runtime.h>
#include <cuda_bf16.h>
#include <cuda_fp16.h>
#include <math.h>
#include <stdint.h>

// Problem constants
#define L_ 12
#define H_ 12
#define C_ 768
#define V_ 50257
#define B_ 2
#define T_ 1024
#define D_ 64
#define M_ (B_*T_)   // 2048 rows

// ---------------------------------------------------------------------------
// Scratch (static device globals) — all-fp16 pipeline
// ---------------------------------------------------------------------------
__device__ float g_bias[T_*T_];
__device__ float g_x   [M_*C_];

__device__ __half g_h16 [M_*C_];
__device__ __half g_qkv16[M_*3*C_];
__device__ __half g_y16 [M_*C_];
__device__ __half g_mlp16[M_*4*C_];

// Layer weights: single fp16 plane (1-product)
__device__ __half g_wa  [L_*3*C_*C_];
__device__ __half g_wp  [L_*C_*C_];
__device__ __half g_wf  [L_*4*C_*C_];
__device__ __half g_wf2 [L_*C_*4*C_];
// LM head: fp16 hi/lo (2-product)
__device__ __half g_wteh[(size_t)V_*C_], g_wtel[(size_t)V_*C_];

// ---------------------------------------------------------------------------
// Helpers
// ---------------------------------------------------------------------------
__device__ __forceinline__ uint32_t smem_u32(const void* p){
    uint32_t a;
    asm("{ .reg .u64 t; cvta.to.shared.u64 t, %1; cvt.u32.u64 %0, t; }":"=r"(a):"l"(p));
    return a;
}
__device__ __forceinline__ void cpa16(uint32_t saddr, const void* gptr){
    asm volatile("cp.async.cg.shared.global [%0], [%1], 16;"::"r"(saddr),"l"(gptr));
}
__device__ __forceinline__ void cpa16z(uint32_t saddr, const void* gptr, int ssz){
    asm volatile("cp.async.cg.shared.global [%0], [%1], 16, %2;"::"r"(saddr),"l"(gptr),"r"(ssz));
}
__device__ __forceinline__ void ldsm4(uint32_t* r, uint32_t addr){
    asm volatile("ldmatrix.sync.aligned.m8n8.x4.shared.b16 {%0,%1,%2,%3}, [%4];"
      : "=r"(r[0]),"=r"(r[1]),"=r"(r[2]),"=r"(r[3]) : "r"(addr));
}
__device__ __forceinline__ void ldsm4t(uint32_t* r, uint32_t addr){
    asm volatile("ldmatrix.sync.aligned.m8n8.x4.trans.shared.b16 {%0,%1,%2,%3}, [%4];"
      : "=r"(r[0]),"=r"(r[1]),"=r"(r[2]),"=r"(r[3]) : "r"(addr));
}
__device__ __forceinline__ void mma16h(float* d, const uint32_t* a, uint32_t b0, uint32_t b1){
    asm volatile("mma.sync.aligned.m16n8k16.row.col.f32.f16.f16.f32 "
      "{%0,%1,%2,%3}, {%4,%5,%6,%7}, {%8,%9}, {%0,%1,%2,%3};"
      : "+f"(d[0]),"+f"(d[1]),"+f"(d[2]),"+f"(d[3])
      : "r"(a[0]),"r"(a[1]),"r"(a[2]),"r"(a[3]),"r"(b0),"r"(b1));
}
__device__ __forceinline__ float exp2a(float x){
    float y; asm("ex2.approx.ftz.f32 %0, %1;":"=f"(y):"f"(x)); return y;
}
__device__ __forceinline__ float rcpa(float x){
    float y; asm("rcp.approx.ftz.f32 %0, %1;":"=f"(y):"f"(x)); return y;
}
__device__ __forceinline__ float gelu_f(float v){
    float u = 0.7978845608028654f*(v + 0.044715f*v*v*v);
    float t = exp2a(u * 2.8853900817779268f);
    return v - v * rcpa(t + 1.0f);
}
__device__ __forceinline__ uint32_t packh2(float c0, float c1){
    uint32_t r; asm("cvt.rn.f16x2.f32 %0, %1, %2;" : "=r"(r) : "f"(c1), "f"(c0));
    return r;
}
#define SWZ(o) ((o) ^ (((o)>>3)&0x70))

// ---------------------------------------------------------------------------
// FP16 GEMM: C = act(A @ B^T + bias) (+resid)
//   A: [M,K] fp16. B: [N,K] fp16 (WPROD=2 adds lo plane).
//   BM=64, 128 threads. BN_ in {128, 64}.
//   Occupancy: WPROD2 -> 2 CTAs/SM; BN128 WPROD1 -> 3 (3-stage); BN64 -> 4.
//   Grid: bm = blockIdx.x*64 (M fastest), bn = blockIdx.y*BN_.
// ---------------------------------------------------------------------------
template<int ACT, bool OUTH, int WPROD, int NSTAGE, int BN_>
__global__ void __launch_bounds__(128, (WPROD==2) ? 2 : ((BN_==64) ? 4 : 3))
mma_gemm(
    const __half* __restrict__ A,
    const __half* __restrict__ Bh, const __half* __restrict__ Bl,
    const float* __restrict__ bias, const float* __restrict__ resid,
    float* __restrict__ Cf, __half* __restrict__ Ch,
    int Nn, int Kk)
{
    constexpr uint32_t ABYTES = 8192;                 // 64 rows x 128B
    constexpr uint32_t BPLANE = (uint32_t)BN_ * 128;  // per B plane
    constexpr uint32_t BBYTES = (WPROD==2) ? 2*BPLANE : BPLANE;
    constexpr uint32_t STAGE  = ABYTES + BBYTES;
    constexpr int NBIT  = (BN_*8)/128;                // B cp iterations
    constexpr int NHALF = BN_/2;                      // cols per warp
    constexpr int NGRP  = NHALF/16;                   // 16-col ldsm groups/warp

    extern __shared__ char ds[];
    const uint32_t sb = (smem_u32(ds) + 1023) & ~1023u;

    const int tid = threadIdx.x, lane = tid & 31, wid = tid >> 5;
    const int bm = blockIdx.x * 64, bn = blockIdx.y * BN_;
    const int NT = Kk >> 6;

    auto cp_stage = [&](int t){
        const uint32_t base = sb + (uint32_t)(t % NSTAGE) * STAGE;
        const int k0 = t << 6;
        #pragma unroll
        for (int i = 0; i < 4; i++){
            int idx = tid + i*128;
            int r = idx >> 3, c = idx & 7;
            uint32_t off = SWZ((uint32_t)(r*128 + c*16));
            cpa16(base + off, A + (size_t)(bm + r) * Kk + k0 + c*8);
        }
        #pragma unroll
        for (int i = 0; i < NBIT; i++){
            int idx = tid + i*128;
            int r = idx >> 3, c = idx & 7;
            uint32_t off = SWZ((uint32_t)(r*128 + c*16));
            int gn = bn + r;
            size_t kb = (size_t)gn * Kk + k0 + c*8;
            int ssz = (gn < Nn) ? 16 : 0;
            cpa16z(base + ABYTES + off, Bh + kb, ssz);
            if (WPROD == 2) cpa16z(base + ABYTES + BPLANE + off, Bl + kb, ssz);
        }
        asm volatile("cp.async.commit_group;":::"memory");
    };

    float acc[2][NGRP*2][4];
    #pragma unroll
    for (int a=0;a<2;a++) for (int b=0;b<NGRP*2;b++) for (int c=0;c<4;c++) acc[a][b][c]=0.f;

    const int m0 = (wid >> 1) * 32, n0 = (wid & 1) * NHALF;
    const uint32_t arow = (uint32_t)(m0 + (lane & 15));
    const uint32_t acol = (uint32_t)((lane >> 4) * 16);
    const uint32_t brow = (uint32_t)(n0 + (lane & 7) + ((lane >> 4) & 1) * 8);
    const uint32_t bcol = (uint32_t)(((lane >> 3) & 1) * 16);

    auto compute = [&](int t){
        const uint32_t base = sb + (uint32_t)(t % NSTAGE) * STAGE;
        #pragma unroll
        for (int ks = 0; ks < 4; ks++){
            const uint32_t kb2 = (uint32_t)(ks * 32);
            uint32_t ah[2][4];
            #pragma unroll
            for (int mt = 0; mt < 2; mt++){
                uint32_t off = SWZ((arow + mt*16)*128 + kb2 + acol);
                ldsm4(ah[mt], base + off);
            }
            #pragma unroll
            for (int g = 0; g < NGRP; g++){
                uint32_t off = SWZ((brow + g*16)*128 + kb2 + bcol);
                uint32_t bh[4], bl[4];
                ldsm4(bh, base + ABYTES + off);
                if (WPROD == 2) ldsm4(bl, base + ABYTES + BPLANE + off);
                #pragma unroll
                for (int mt = 0; mt < 2; mt++){
                    #pragma unroll
                    for (int sub = 0; sub < 2; sub++){
                        float* d = acc[mt][g*2 + sub];
                        mma16h(d, ah[mt], bh[sub*2], bh[sub*2+1]);
                        if (WPROD == 2) mma16h(d, ah[mt], bl[sub*2], bl[sub*2+1]);
                    }
                }
            }
        }
    };

    cp_stage(0);
    if (NT > 1) cp_stage(1);
    for (int t = 0; t < NT; t++){
        if (t + 1 < NT) asm volatile("cp.async.wait_group 1;":::"memory");
        else            asm volatile("cp.async.wait_group 0;":::"memory");
        __syncthreads();
        compute(t);
        if (NSTAGE == 2) __syncthreads();
        if (t + 2 < NT) cp_stage(t + 2);
    }

    #pragma unroll
    for (int mt = 0; mt < 2; mt++){
        #pragma unroll
        for (int h2 = 0; h2 < 2; h2++){
            int row = bm + m0 + mt*16 + (lane>>2) + h2*8;
            float* crow = OUTH ? nullptr : (Cf + (size_t)row * Nn);
            const float* rrow = resid ? resid + (size_t)row * Nn : nullptr;
            #pragma unroll
            for (int nt = 0; nt < NGRP*2; nt++){
                int col = bn + n0 + nt*8 + (lane&3)*2;
                if (col >= Nn) continue;
                float v0 = acc[mt][nt][h2*2+0];
                float v1 = acc[mt][nt][h2*2+1];
                bool has1 = (col + 1 < Nn);
                if (bias){ v0 += bias[col]; if (has1) v1 += bias[col+1]; }
                if (ACT == 1){ v0 = gelu_f(v0); v1 = gelu_f(v1); }
                if (rrow){ v0 += rrow[col]; if (has1) v1 += rrow[col+1]; }
                if (OUTH){
                    *reinterpret_cast<uint32_t*>(Ch + (size_t)row * Nn + col) = packh2(v0, v1);
                } else if (((Nn & 1) == 0) && has1){
                    float2 st; st.x = v0; st.y = v1;
                    *reinterpret_cast<float2*>(crow + col) = st;
                } else {
                    crow[col] = v0;
                    if (has1) crow[col + 1] = v1;
                }
            }
        }
    }
}

// ---------------------------------------------------------------------------
// FlashAttention, plain fp16: one block = 128 q-rows x one (b,h).
// Causal group-skip: fully-masked 16-col groups contribute exact zeros,
// so their QK/PV MMAs are skipped with bitwise-identical results.
// smem: Q 16K | K 2st 32K | V 2st 32K = 80K -> 2 CTAs/SM.
// ---------------------------------------------------------------------------
#define FLASH_SMEM (81920 + 1024)

__global__ void __launch_bounds__(256) flash_kernel(
    const __half* __restrict__ qkv,
    const float* __restrict__ bias2,
    __half* __restrict__ y)
{
    extern __shared__ char ds[];
    const uint32_t sb = (smem_u32(ds) + 1023) & ~1023u;
    const uint32_t sQ = sb;

    const int tid = threadIdx.x, lane = tid & 31, w = tid >> 5;
    const int bh = blockIdx.y, b = bh / H_, h = bh % H_;
    const int i0 = (int)(gridDim.x - 1 - blockIdx.x) * 128;
    const int nj = (i0 >> 7) + 1;
    const int imax_w = i0 + w*16 + 15;   // max query row this warp owns

    const __half* qp = qkv + (size_t)b * T_ * 3 * C_ + h * D_;
    const __half* kp = qp + C_;
    const __half* vp = qp + 2*C_;

    auto cp_q = [&](){
        #pragma unroll
        for (int i = 0; i < 4; i++){
            int idx = tid + i*256;
            int r = idx >> 3, c = idx & 7;
            uint32_t off = SWZ((uint32_t)(r*128 + c*16));
            cpa16(sQ + off, qp + (size_t)(i0 + r) * 3 * C_ + c*8);
        }
    };
    auto cp_kv = [&](int jt){
        int st = jt & 1, j0 = jt << 7;
        uint32_t kb = sb + 16384 + (uint32_t)st * 16384;
        uint32_t vb = sb + 49152 + (uint32_t)st * 16384;
        #pragma unroll
        for (int i = 0; i < 4; i++){
            int idx = tid + i*256;
            int r = idx >> 3, c = idx & 7;
            uint32_t off = SWZ((uint32_t)(r*128 + c*16));
            size_t g = (size_t)(j0 + r) * 3 * C_ + c*8;
            cpa16(kb + off, kp + g);
            cpa16(vb + off, vp + g);
        }
        asm volatile("cp.async.commit_group;":::"memory");
    };

    cp_q(); cp_kv(0);
    if (nj > 1) cp_kv(1);
    if (nj > 1) asm volatile("cp.async.wait_group 1;":::"memory");
    else        asm volatile("cp.async.wait_group 0;":::"memory");
    __syncthreads();

    uint32_t qf[4][4];
    {
        uint32_t arow = (uint32_t)(w*16 + (lane & 15));
        uint32_t acol = (uint32_t)((lane >> 4) * 16);
        #pragma unroll
        for (int kt = 0; kt < 4; kt++){
            uint32_t off = SWZ(arow*128 + (uint32_t)kt*32 + acol);
            ldsm4(qf[kt], sQ + off);
        }
    }

    float O[8][4];
    #pragma unroll
    for (int i=0;i<8;i++) for (int j=0;j<4;j++) O[i][j]=0.f;
    float mr0 = -INFINITY, mr1 = -INFINITY, l0 = 0.f, l1 = 0.f;

    const float SC = 0.125f * 1.4426950408889634f;
    const uint32_t brow = (uint32_t)((lane & 7) + ((lane >> 4) & 1) * 8);
    const uint32_t bcol = (uint32_t)(((lane >> 3) & 1) * 16);
    const uint32_t vrow = (uint32_t)((lane & 7) + ((lane >> 3) & 1) * 8);
    const uint32_t vcol = (uint32_t)((lane >> 4) * 16);

    for (int jt = 0; jt < nj; jt++){
        const int st = jt & 1, j0 = jt << 7;
        const uint32_t kb = sb + 16384 + (uint32_t)st * 16384;
        const uint32_t vb = sb + 49152 + (uint32_t)st * 16384;
        // groups with j0+g*16 > imax_w are fully masked (exp -> exact 0)
        const int gmax = (jt == nj-1) ? ((imax_w - j0) >> 4) : 7;

        float S[16][4];
        #pragma unroll
        for (int i=0;i<16;i++) for (int j=0;j<4;j++) S[i][j]=0.f;
        #pragma unroll
        for (int kt = 0; kt < 4; kt++){
            const uint32_t kb2 = (uint32_t)kt * 32;
            #pragma unroll
            for (int g = 0; g < 8; g++){
                if (g > gmax) break;
                uint32_t off = SWZ((brow + g*16)*128 + kb2 + bcol);
                uint32_t kf[4];
                ldsm4(kf, kb + off);
                mma16h(S[g*2    ], qf[kt], kf[0], kf[1]);
                mma16h(S[g*2 + 1], qf[kt], kf[2], kf[3]);
            }
        }

        {
            int gi = i0 + w*16 + (lane >> 2);
            int gjb = j0 + (lane & 3) * 2;
            const float* b0 = bias2 + (size_t)gi * T_ + gjb;
            const float* b1 = bias2 + (size_t)(gi + 8) * T_ + gjb;
            #pragma unroll
            for (int nt = 0; nt < 16; nt++){
                float2 ba = *reinterpret_cast<const float2*>(b0 + nt*8);
                float2 bb = *reinterpret_cast<const float2*>(b1 + nt*8);
                S[nt][0] = S[nt][0]*SC + ba.x;
                S[nt][1] = S[nt][1]*SC + ba.y;
                S[nt][2] = S[nt][2]*SC + bb.x;
                S[nt][3] = S[nt][3]*SC + bb.y;
            }
        }

        float mn0 = mr0, mn1 = mr1;
        #pragma unroll
        for (int nt = 0; nt < 16; nt++){
            mn0 = fmaxf(mn0, fmaxf(S[nt][0], S[nt][1]));
            mn1 = fmaxf(mn1, fmaxf(S[nt][2], S[nt][3]));
        }
        mn0 = fmaxf(mn0, __shfl_xor_sync(0xffffffffu, mn0, 1));
        mn0 = fmaxf(mn0, __shfl_xor_sync(0xffffffffu, mn0, 2));
        mn1 = fmaxf(mn1, __shfl_xor_sync(0xffffffffu, mn1, 1));
        mn1 = fmaxf(mn1, __shfl_xor_sync(0xffffffffu, mn1, 2));
        float sc0 = exp2a(mr0 - mn0), sc1 = exp2a(mr1 - mn1);
        mr0 = mn0; mr1 = mn1;
        float rs0 = 0.f, rs1 = 0.f;
        #pragma unroll
        for (int nt = 0; nt < 16; nt++){
            S[nt][0] = exp2a(S[nt][0] - mn0);
            S[nt][1] = exp2a(S[nt][1] - mn0);
            S[nt][2] = exp2a(S[nt][2] - mn1);
            S[nt][3] = exp2a(S[nt][3] - mn1);
            rs0 += S[nt][0] + S[nt][1];
            rs1 += S[nt][2] + S[nt][3];
        }
        rs0 += __shfl_xor_sync(0xffffffffu, rs0, 1);
        rs0 += __shfl_xor_sync(0xffffffffu, rs0, 2);
        rs1 += __shfl_xor_sync(0xffffffffu, rs1, 1);
        rs1 += __shfl_xor_sync(0xffffffffu, rs1, 2);
        l0 = l0 * sc0 + rs0;
        l1 = l1 * sc1 + rs1;
        #pragma unroll
        for (int nt = 0; nt < 8; nt++){
            O[nt][0] *= sc0; O[nt][1] *= sc0;
            O[nt][2] *= sc1; O[nt][3] *= sc1;
        }

        #pragma unroll
        for (int g = 0; g < 8; g++){
            if (g > gmax) break;   // P rows are exact zeros beyond gmax
            uint32_t pa[4];
            pa[0] = packh2(S[2*g  ][0], S[2*g  ][1]);
            pa[1] = packh2(S[2*g  ][2], S[2*g  ][3]);
            pa[2] = packh2(S[2*g+1][0], S[2*g+1][1]);
            pa[3] = packh2(S[2*g+1][2], S[2*g+1][3]);
            #pragma unroll
            for (int dv = 0; dv < 4; dv++){
                uint32_t off = SWZ((vrow + g*16)*128 + (uint32_t)dv*32 + vcol);
                uint32_t vf[4];
                ldsm4t(vf, vb + off);
                mma16h(O[dv*2    ], pa, vf[0], vf[1]);
                mma16h(O[dv*2 + 1], pa, vf[2], vf[3]);
            }
        }

        __syncthreads();
        if (jt + 2 < nj) cp_kv(jt + 2);
        if (jt + 1 < nj){
            if (jt + 2 < nj) asm volatile("cp.async.wait_group 1;":::"memory");
            else             asm volatile("cp.async.wait_group 0;":::"memory");
            __syncthreads();
        }
    }

    float li0 = 1.f / l0, li1 = 1.f / l1;
    int r0 = i0 + w*16 + (lane >> 2);
    size_t base0 = (size_t)b * T_ * C_ + (size_t)r0 * C_ + h * D_;
    size_t base1 = base0 + (size_t)8 * C_;
    #pragma unroll
    for (int nt = 0; nt < 8; nt++){
        int col = nt*8 + (lane & 3)*2;
        *reinterpret_cast<uint32_t*>(y + base0 + col) = packh2(O[nt][0]*li0, O[nt][1]*li0);
        *reinterpret_cast<uint32_t*>(y + base1 + col) = packh2(O[nt][2]*li1, O[nt][3]*li1);
    }
}

// ---------------------------------------------------------------------------
// Weight prep: transpose [K,N]->[N,K], single fp16 plane
// ---------------------------------------------------------------------------
__global__ void wtrans16_kernel(const float* __restrict__ in,
                                __half* __restrict__ oh, int K, int N){
    __shared__ float t[32][33];
    size_t lb = (size_t)blockIdx.z * K * N;
    const float* inp = in + lb;
    int kb = blockIdx.y*32, nb = blockIdx.x*32;
    int tx = threadIdx.x, ty = threadIdx.y;
    #pragma unroll
    for (int j = 0; j < 4; j++)
        t[ty + 8*j][tx] = inp[(size_t)(kb + ty + 8*j) * N + nb + tx];
    __syncthreads();
    #pragma unroll
    for (int j = 0; j < 4; j++){
        int n = nb + ty + 8*j, k = kb + tx;
        oh[lb + (size_t)n * K + k] = __float2half_rn(t[tx][ty + 8*j]);
    }
}

// fp16 hi/lo split for wte (already [N,K])
__global__ void split_f16_kernel(const float* __restrict__ in,
                                 __half* __restrict__ ohi, __half* __restrict__ olo, int n){
    int i = blockIdx.x * 256 + threadIdx.x;
    if (i < n){
        float v = in[i];
        __half h = __float2half_rn(v);
        ohi[i] = h;
        olo[i] = __float2half_rn(v - __half2float(h));
    }
}

// ---------------------------------------------------------------------------
// FIRE bias (pre-scaled by log2e)
// ---------------------------------------------------------------------------
__global__ void fire_bias_kernel(const float* __restrict__ log_c,
                                 const float* __restrict__ v1w, const float* __restrict__ v1b,
                                 const float* __restrict__ v2w, const float* __restrict__ v2b,
                                 const float* __restrict__ v3w, const float* __restrict__ v3b,
                                 float* __restrict__ bias) {
    __shared__ float s1w[32], s1b[32], s2w[1024], s2b[32], s3w[32];
    __shared__ float s3b, sc;
    int tid = threadIdx.x;
    if (tid < 32) { s1w[tid] = v1w[tid]; s1b[tid] = v1b[tid]; s2b[tid] = v2b[tid]; s3w[tid] = v3w[tid]; }
    for (int i = tid; i < 1024; i += blockDim.x) s2w[i] = v2w[i];
    if (tid == 0) { s3b = v3b[0]; sc = expf(log_c[0]); }
    __syncthreads();

    int idx = blockIdx.x * blockDim.x + tid;
    if (idx >= T_*T_) return;
    int i = idx / T_, j = idx % T_;
    if (j > i) { bias[idx] = -1e30f; return; }

    float c = sc;
    float fi = (float)(i + 1), fj = (float)(j + 1);
    float pv = logf(c * (fi - fj) + 1.0f) / logf(c * fi + 1.0f);

    float h1[32];
    #pragma unroll
    for (int k = 0; k < 32; k++) h1[k] = fmaxf(pv * s1w[k] + s1b[k], 0.f);
    float out = s3b;
    #pragma unroll
    for (int k2 = 0; k2 < 32; k2++) {
        float a = s2b[k2];
        #pragma unroll
        for (int k1 = 0; k1 < 32; k1++) a += h1[k1] * s2w[k1*32 + k2];
        out += fmaxf(a, 0.f) * s3w[k2];
    }
    bias[idx] = out * 1.4426950408889634f;
}

// ---------------------------------------------------------------------------
// Embedding gather
// ---------------------------------------------------------------------------
__global__ void embed_kernel(const int* __restrict__ idx, const float* __restrict__ wte,
                             float* __restrict__ x) {
    int row = blockIdx.x;
    const float* src = wte + (size_t)idx[row] * C_;
    float* dst = x + (size_t)row * C_;
    for (int c = threadIdx.x; c < C_; c += blockDim.x) dst[c] = src[c];
}

// ---------------------------------------------------------------------------
// LayerNorm: warp-per-row -> fp16 plane
// ---------------------------------------------------------------------------
__global__ void __launch_bounds__(256) ln_kernel(
    const float* __restrict__ x, const float* __restrict__ g,
    const float* __restrict__ b, __half* __restrict__ oh) {
    const int wid = threadIdx.x >> 5, lane = threadIdx.x & 31;
    const int row = blockIdx.x * 8 + wid;
    const float4* xr = reinterpret_cast<const float4*>(x + (size_t)row * C_);
    const float4* g4 = reinterpret_cast<const float4*>(g);
    const float4* b4 = reinterpret_cast<const float4*>(b);

    float4 v[6];
    float s = 0.f;
    #pragma unroll
    for (int c = 0; c < 6; c++){
        v[c] = xr[lane + c*32];
        s += v[c].x + v[c].y + v[c].z + v[c].w;
    }
    #pragma unroll
    for (int o = 16; o > 0; o >>= 1) s += __shfl_xor_sync(0xffffffffu, s, o);
    const float mean = s * (1.0f / C_);

    float q = 0.f;
    #pragma unroll
    for (int c = 0; c < 6; c++){
        v[c].x -= mean; v[c].y -= mean; v[c].z -= mean; v[c].w -= mean;
        q += v[c].x*v[c].x + v[c].y*v[c].y + v[c].z*v[c].z + v[c].w*v[c].w;
    }
    #pragma unroll
    for (int o = 16; o > 0; o >>= 1) q += __shfl_xor_sync(0xffffffffu, q, o);
    const float rs = rsqrtf(q * (1.0f / C_) + 1e-5f);

    const size_t base = (size_t)row * C_;
    #pragma unroll
    for (int c = 0; c < 6; c++){
        int c4 = lane + c*32;
        float4 gg = g4[c4], bb = b4[c4];
        uint2 hh;
        hh.x = packh2(v[c].x*rs*gg.x + bb.x, v[c].y*rs*gg.y + bb.y);
        hh.y = packh2(v[c].z*rs*gg.z + bb.z, v[c].w*rs*gg.w + bb.w);
        *reinterpret_cast<uint2*>(oh + base + c4*4) = hh;
    }
}

// ---------------------------------------------------------------------------
// Launch
// ---------------------------------------------------------------------------
extern "C" void kernel_launch(void* const* d_in, const int* in_sizes, int n_in,
                              void* d_out, int out_size) {
    int o = (n_in >= 2 && in_sizes[1] == 1) ? 1 : 0;

    const int*   idx   = (const int*)  d_in[0];
    const float* wte   = (const float*)d_in[1 + o];
    const float* log_c = (const float*)d_in[2 + o];
    const float* v1w   = (const float*)d_in[3 + o];
    const float* v1b   = (const float*)d_in[4 + o];
    const float* v2w   = (const float*)d_in[5 + o];
    const float* v2b   = (const float*)d_in[6 + o];
    const float* v3w   = (const float*)d_in[7 + o];
    const float* v3b   = (const float*)d_in[8 + o];
    const float* ln1g  = (const float*)d_in[9 + o];
    const float* ln1b  = (const float*)d_in[10 + o];
    const float* attnw = (const float*)d_in[11 + o];
    const float* attnb = (const float*)d_in[12 + o];
    const float* projw = (const float*)d_in[13 + o];
    const float* projb = (const float*)d_in[14 + o];
    const float* ln2g  = (const float*)d_in[15 + o];
    const float* ln2b  = (const float*)d_in[16 + o];
    const float* fcw   = (const float*)d_in[17 + o];
    const float* fcb   = (const float*)d_in[18 + o];
    const float* fc2w  = (const float*)d_in[19 + o];
    const float* fc2b  = (const float*)d_in[20 + o];
    const float* lnfg  = (const float*)d_in[21 + o];
    const float* lnfb  = (const float*)d_in[22 + o];

    float *bias, *x;
    __half *h16, *qkv16, *y16, *mlp16;
    __half *wa, *wp, *wf, *wf2, *wteh, *wtel;
    cudaGetSymbolAddress((void**)&bias,  g_bias);
    cudaGetSymbolAddress((void**)&x,     g_x);
    cudaGetSymbolAddress((void**)&h16,   g_h16);
    cudaGetSymbolAddress((void**)&qkv16, g_qkv16);
    cudaGetSymbolAddress((void**)&y16,   g_y16);
    cudaGetSymbolAddress((void**)&mlp16, g_mlp16);
    cudaGetSymbolAddress((void**)&wa,    g_wa);
    cudaGetSymbolAddress((void**)&wp,    g_wp);
    cudaGetSymbolAddress((void**)&wf,    g_wf);
    cudaGetSymbolAddress((void**)&wf2,   g_wf2);
    cudaGetSymbolAddress((void**)&wteh,  g_wteh);
    cudaGetSymbolAddress((void**)&wtel,  g_wtel);

    // smem sizes (R13-validated configs)
    const int SMQ = 3*24576 + 1024;   // BN128, WPROD1, 3 stages -> 3 CTAs/SM
    const int SMP = 3*16384 + 1024;   // BN64,  WPROD1, 3 stages -> 4 CTAs/SM
    const int SML = 2*40960 + 1024;   // BN128, WPROD2, 2 stages -> 2 CTAs/SM

    cudaFuncSetAttribute(mma_gemm<0,true ,1,3,128>, cudaFuncAttributeMaxDynamicSharedMemorySize, SMQ);
    cudaFuncSetAttribute(mma_gemm<1,true ,1,3,128>, cudaFuncAttributeMaxDynamicSharedMemorySize, SMQ);
    cudaFuncSetAttribute(mma_gemm<0,false,1,3, 64>, cudaFuncAttributeMaxDynamicSharedMemorySize, SMP);
    cudaFuncSetAttribute(mma_gemm<0,false,2,2,128>, cudaFuncAttributeMaxDynamicSharedMemorySize, SML);
    cudaFuncSetAttribute(flash_kernel,              cudaFuncAttributeMaxDynamicSharedMemorySize, FLASH_SMEM);

    // 1. FIRE bias + embedding + weight prep
    fire_bias_kernel<<<(T_*T_ + 255) / 256, 256>>>(log_c, v1w, v1b, v2w, v2b, v3w, v3b, bias);
    embed_kernel<<<M_, 256>>>(idx, wte, x);
    {
        dim3 tb(32, 8);
        wtrans16_kernel<<<dim3(3*C_/32,  C_/32,  L_), tb>>>(attnw, wa,  C_,   3*C_);
        wtrans16_kernel<<<dim3(C_/32,    C_/32,  L_), tb>>>(projw, wp,  C_,   C_);
        wtrans16_kernel<<<dim3(4*C_/32,  C_/32,  L_), tb>>>(fcw,   wf,  C_,   4*C_);
        wtrans16_kernel<<<dim3(C_/32,  4*C_/32,  L_), tb>>>(fc2w,  wf2, 4*C_, C_);
        split_f16_kernel<<<(V_*C_ + 255)/256, 256>>>(wte, wteh, wtel, V_*C_);
    }

    // 2. Transformer layers
    const dim3 g_qkvd(M_/64, 3*C_/128);
    const dim3 g_cc  (M_/64, C_/64);
    const dim3 g_fc  (M_/64, 4*C_/128);
    const dim3 g_fl  (T_/128, B_*H_);

    for (int l = 0; l < L_; l++) {
        size_t wao = (size_t)l*3*C_*C_, wpo = (size_t)l*C_*C_, wfo = (size_t)l*4*C_*C_;
        ln_kernel<<<M_/8, 256>>>(x, ln1g + (size_t)l*C_, ln1b + (size_t)l*C_, h16);
        mma_gemm<0,true,1,3,128><<<g_qkvd, 128, SMQ>>>(h16, wa + wao, nullptr,
                                                       attnb + (size_t)l*3*C_, nullptr,
                                                       nullptr, qkv16, 3*C_, C_);
        flash_kernel<<<g_fl, 256, FLASH_SMEM>>>(qkv16, bias, y16);
        mma_gemm<0,false,1,3,64><<<g_cc, 128, SMP>>>(y16, wp + wpo, nullptr,
                                                     projb + (size_t)l*C_, x,
                                                     x, nullptr, C_, C_);
        ln_kernel<<<M_/8, 256>>>(x, ln2g + (size_t)l*C_, ln2b + (size_t)l*C_, h16);
        mma_gemm<1,true,1,3,128><<<g_fc, 128, SMQ>>>(h16, wf + wfo, nullptr,
                                                     fcb + (size_t)l*4*C_, nullptr,
                                                     nullptr, mlp16, 4*C_, C_);
        mma_gemm<0,false,1,3,64><<<g_cc, 128, SMP>>>(mlp16, wf2 + wfo, nullptr,
                                                     fc2b + (size_t)l*C_, x,
                                                     x, nullptr, C_, 4*C_);
    }

    // 3. Final LN + tied LM head (fp16 2-product)
    ln_kernel<<<M_/8, 256>>>(x, lnfg, lnfb, h16);
    const dim3 g_lm(M_/64, (V_ + 127)/128);
    mma_gemm<0,false,2,2,128><<<g_lm, 128, SML>>>(h16, wteh, wtel,
                                                  nullptr, nullptr,
                                                  (float*)d_out, nullptr, V_, C_);
}

// round 16
// speedup vs baseline: 1.0424x; 1.0424x over previous
#include <cuda_runtime.h>
#include <cuda_bf16.h>
#include <cuda_fp16.h>
#include <math.h>
#include <stdint.h>

// Problem constants
#define L_ 12
#define H_ 12
#define C_ 768
#define V_ 50257
#define B_ 2
#define T_ 1024
#define D_ 64
#define M_ (B_*T_)   // 2048 rows

// ---------------------------------------------------------------------------
// Scratch (static device globals) — all-fp16 pipeline
// ---------------------------------------------------------------------------
__device__ float g_bias[T_*T_];
__device__ float g_x   [M_*C_];

__device__ __half g_h16 [M_*C_];
__device__ __half g_qkv16[M_*3*C_];
__device__ __half g_y16 [M_*C_];
__device__ __half g_mlp16[M_*4*C_];

// Layer weights: single fp16 plane (1-product)
__device__ __half g_wa  [L_*3*C_*C_];
__device__ __half g_wp  [L_*C_*C_];
__device__ __half g_wf  [L_*4*C_*C_];
__device__ __half g_wf2 [L_*C_*4*C_];
// LM head: fp16 hi/lo (2-product)
__device__ __half g_wteh[(size_t)V_*C_], g_wtel[(size_t)V_*C_];

// ---------------------------------------------------------------------------
// Helpers
// ---------------------------------------------------------------------------
__device__ __forceinline__ uint32_t smem_u32(const void* p){
    uint32_t a;
    asm("{ .reg .u64 t; cvta.to.shared.u64 t, %1; cvt.u32.u64 %0, t; }":"=r"(a):"l"(p));
    return a;
}
__device__ __forceinline__ void cpa16(uint32_t saddr, const void* gptr){
    asm volatile("cp.async.cg.shared.global [%0], [%1], 16;"::"r"(saddr),"l"(gptr));
}
__device__ __forceinline__ void cpa16z(uint32_t saddr, const void* gptr, int ssz){
    asm volatile("cp.async.cg.shared.global [%0], [%1], 16, %2;"::"r"(saddr),"l"(gptr),"r"(ssz));
}
__device__ __forceinline__ void ldsm4(uint32_t* r, uint32_t addr){
    asm volatile("ldmatrix.sync.aligned.m8n8.x4.shared.b16 {%0,%1,%2,%3}, [%4];"
      : "=r"(r[0]),"=r"(r[1]),"=r"(r[2]),"=r"(r[3]) : "r"(addr));
}
__device__ __forceinline__ void ldsm4t(uint32_t* r, uint32_t addr){
    asm volatile("ldmatrix.sync.aligned.m8n8.x4.trans.shared.b16 {%0,%1,%2,%3}, [%4];"
      : "=r"(r[0]),"=r"(r[1]),"=r"(r[2]),"=r"(r[3]) : "r"(addr));
}
__device__ __forceinline__ void mma16h(float* d, const uint32_t* a, uint32_t b0, uint32_t b1){
    asm volatile("mma.sync.aligned.m16n8k16.row.col.f32.f16.f16.f32 "
      "{%0,%1,%2,%3}, {%4,%5,%6,%7}, {%8,%9}, {%0,%1,%2,%3};"
      : "+f"(d[0]),"+f"(d[1]),"+f"(d[2]),"+f"(d[3])
      : "r"(a[0]),"r"(a[1]),"r"(a[2]),"r"(a[3]),"r"(b0),"r"(b1));
}
__device__ __forceinline__ float exp2a(float x){
    float y; asm("ex2.approx.ftz.f32 %0, %1;":"=f"(y):"f"(x)); return y;
}
__device__ __forceinline__ float rcpa(float x){
    float y; asm("rcp.approx.ftz.f32 %0, %1;":"=f"(y):"f"(x)); return y;
}
__device__ __forceinline__ float gelu_f(float v){
    float u = 0.7978845608028654f*(v + 0.044715f*v*v*v);
    float t = exp2a(u * 2.8853900817779268f);
    return v - v * rcpa(t + 1.0f);
}
__device__ __forceinline__ uint32_t packh2(float c0, float c1){
    uint32_t r; asm("cvt.rn.f16x2.f32 %0, %1, %2;" : "=r"(r) : "f"(c1), "f"(c0));
    return r;
}
#define SWZ(o) ((o) ^ (((o)>>3)&0x70))

// ---------------------------------------------------------------------------
// FP16 GEMM: C = act(A @ B^T + bias) (+resid)
//   A: [M,K] fp16. B: [N,K] fp16 (WPROD=2 adds lo plane).
//   BM=64, 128 threads. BN_ in {128, 64}.
//   Occupancy: WPROD2 -> 2 CTAs/SM; BN128 WPROD1 -> 3 (3-stage); BN64 -> 4.
//   Grid: bm = blockIdx.x*64 (M fastest), bn = blockIdx.y*BN_.
// ---------------------------------------------------------------------------
template<int ACT, bool OUTH, int WPROD, int NSTAGE, int BN_>
__global__ void __launch_bounds__(128, (WPROD==2) ? 2 : ((BN_==64) ? 4 : 3))
mma_gemm(
    const __half* __restrict__ A,
    const __half* __restrict__ Bh, const __half* __restrict__ Bl,
    const float* __restrict__ bias, const float* __restrict__ resid,
    float* __restrict__ Cf, __half* __restrict__ Ch,
    int Nn, int Kk)
{
    constexpr uint32_t ABYTES = 8192;                 // 64 rows x 128B
    constexpr uint32_t BPLANE = (uint32_t)BN_ * 128;  // per B plane
    constexpr uint32_t BBYTES = (WPROD==2) ? 2*BPLANE : BPLANE;
    constexpr uint32_t STAGE  = ABYTES + BBYTES;
    constexpr int NBIT  = (BN_*8)/128;                // B cp iterations
    constexpr int NHALF = BN_/2;                      // cols per warp
    constexpr int NGRP  = NHALF/16;                   // 16-col ldsm groups/warp

    extern __shared__ char ds[];
    const uint32_t sb = (smem_u32(ds) + 1023) & ~1023u;

    const int tid = threadIdx.x, lane = tid & 31, wid = tid >> 5;
    const int bm = blockIdx.x * 64, bn = blockIdx.y * BN_;
    const int NT = Kk >> 6;

    auto cp_stage = [&](int t){
        const uint32_t base = sb + (uint32_t)(t % NSTAGE) * STAGE;
        const int k0 = t << 6;
        #pragma unroll
        for (int i = 0; i < 4; i++){
            int idx = tid + i*128;
            int r = idx >> 3, c = idx & 7;
            uint32_t off = SWZ((uint32_t)(r*128 + c*16));
            cpa16(base + off, A + (size_t)(bm + r) * Kk + k0 + c*8);
        }
        #pragma unroll
        for (int i = 0; i < NBIT; i++){
            int idx = tid + i*128;
            int r = idx >> 3, c = idx & 7;
            uint32_t off = SWZ((uint32_t)(r*128 + c*16));
            int gn = bn + r;
            size_t kb = (size_t)gn * Kk + k0 + c*8;
            int ssz = (gn < Nn) ? 16 : 0;
            cpa16z(base + ABYTES + off, Bh + kb, ssz);
            if (WPROD == 2) cpa16z(base + ABYTES + BPLANE + off, Bl + kb, ssz);
        }
        asm volatile("cp.async.commit_group;":::"memory");
    };

    float acc[2][NGRP*2][4];
    #pragma unroll
    for (int a=0;a<2;a++) for (int b=0;b<NGRP*2;b++) for (int c=0;c<4;c++) acc[a][b][c]=0.f;

    const int m0 = (wid >> 1) * 32, n0 = (wid & 1) * NHALF;
    const uint32_t arow = (uint32_t)(m0 + (lane & 15));
    const uint32_t acol = (uint32_t)((lane >> 4) * 16);
    const uint32_t brow = (uint32_t)(n0 + (lane & 7) + ((lane >> 4) & 1) * 8);
    const uint32_t bcol = (uint32_t)(((lane >> 3) & 1) * 16);

    auto compute = [&](int t){
        const uint32_t base = sb + (uint32_t)(t % NSTAGE) * STAGE;
        #pragma unroll
        for (int ks = 0; ks < 4; ks++){
            const uint32_t kb2 = (uint32_t)(ks * 32);
            uint32_t ah[2][4];
            #pragma unroll
            for (int mt = 0; mt < 2; mt++){
                uint32_t off = SWZ((arow + mt*16)*128 + kb2 + acol);
                ldsm4(ah[mt], base + off);
            }
            #pragma unroll
            for (int g = 0; g < NGRP; g++){
                uint32_t off = SWZ((brow + g*16)*128 + kb2 + bcol);
                uint32_t bh[4], bl[4];
                ldsm4(bh, base + ABYTES + off);
                if (WPROD == 2) ldsm4(bl, base + ABYTES + BPLANE + off);
                #pragma unroll
                for (int mt = 0; mt < 2; mt++){
                    #pragma unroll
                    for (int sub = 0; sub < 2; sub++){
                        float* d = acc[mt][g*2 + sub];
                        mma16h(d, ah[mt], bh[sub*2], bh[sub*2+1]);
                        if (WPROD == 2) mma16h(d, ah[mt], bl[sub*2], bl[sub*2+1]);
                    }
                }
            }
        }
    };

    cp_stage(0);
    if (NT > 1) cp_stage(1);
    for (int t = 0; t < NT; t++){
        if (t + 1 < NT) asm volatile("cp.async.wait_group 1;":::"memory");
        else            asm volatile("cp.async.wait_group 0;":::"memory");
        __syncthreads();
        compute(t);
        if (NSTAGE == 2) __syncthreads();
        if (t + 2 < NT) cp_stage(t + 2);
    }

    #pragma unroll
    for (int mt = 0; mt < 2; mt++){
        #pragma unroll
        for (int h2 = 0; h2 < 2; h2++){
            int row = bm + m0 + mt*16 + (lane>>2) + h2*8;
            float* crow = OUTH ? nullptr : (Cf + (size_t)row * Nn);
            const float* rrow = resid ? resid + (size_t)row * Nn : nullptr;
            #pragma unroll
            for (int nt = 0; nt < NGRP*2; nt++){
                int col = bn + n0 + nt*8 + (lane&3)*2;
                if (col >= Nn) continue;
                float v0 = acc[mt][nt][h2*2+0];
                float v1 = acc[mt][nt][h2*2+1];
                bool has1 = (col + 1 < Nn);
                if (bias){ v0 += bias[col]; if (has1) v1 += bias[col+1]; }
                if (ACT == 1){ v0 = gelu_f(v0); v1 = gelu_f(v1); }
                if (rrow){ v0 += rrow[col]; if (has1) v1 += rrow[col+1]; }
                if (OUTH){
                    *reinterpret_cast<uint32_t*>(Ch + (size_t)row * Nn + col) = packh2(v0, v1);
                } else if (((Nn & 1) == 0) && has1){
                    float2 st; st.x = v0; st.y = v1;
                    *reinterpret_cast<float2*>(crow + col) = st;
                } else {
                    crow[col] = v0;
                    if (has1) crow[col + 1] = v1;
                }
            }
        }
    }
}

// ---------------------------------------------------------------------------
// FlashAttention, plain fp16 (R13 configuration — no group-skip).
// smem: Q 16K | K 2st 32K | V 2st 32K = 80K -> 2 CTAs/SM.
// ---------------------------------------------------------------------------
#define FLASH_SMEM (81920 + 1024)

__global__ void __launch_bounds__(256) flash_kernel(
    const __half* __restrict__ qkv,
    const float* __restrict__ bias2,
    __half* __restrict__ y)
{
    extern __shared__ char ds[];
    const uint32_t sb = (smem_u32(ds) + 1023) & ~1023u;
    const uint32_t sQ = sb;

    const int tid = threadIdx.x, lane = tid & 31, w = tid >> 5;
    const int bh = blockIdx.y, b = bh / H_, h = bh % H_;
    const int i0 = (int)(gridDim.x - 1 - blockIdx.x) * 128;
    const int nj = (i0 >> 7) + 1;

    const __half* qp = qkv + (size_t)b * T_ * 3 * C_ + h * D_;
    const __half* kp = qp + C_;
    const __half* vp = qp + 2*C_;

    auto cp_q = [&](){
        #pragma unroll
        for (int i = 0; i < 4; i++){
            int idx = tid + i*256;
            int r = idx >> 3, c = idx & 7;
            uint32_t off = SWZ((uint32_t)(r*128 + c*16));
            cpa16(sQ + off, qp + (size_t)(i0 + r) * 3 * C_ + c*8);
        }
    };
    auto cp_kv = [&](int jt){
        int st = jt & 1, j0 = jt << 7;
        uint32_t kb = sb + 16384 + (uint32_t)st * 16384;
        uint32_t vb = sb + 49152 + (uint32_t)st * 16384;
        #pragma unroll
        for (int i = 0; i < 4; i++){
            int idx = tid + i*256;
            int r = idx >> 3, c = idx & 7;
            uint32_t off = SWZ((uint32_t)(r*128 + c*16));
            size_t g = (size_t)(j0 + r) * 3 * C_ + c*8;
            cpa16(kb + off, kp + g);
            cpa16(vb + off, vp + g);
        }
        asm volatile("cp.async.commit_group;":::"memory");
    };

    cp_q(); cp_kv(0);
    if (nj > 1) cp_kv(1);
    if (nj > 1) asm volatile("cp.async.wait_group 1;":::"memory");
    else        asm volatile("cp.async.wait_group 0;":::"memory");
    __syncthreads();

    uint32_t qf[4][4];
    {
        uint32_t arow = (uint32_t)(w*16 + (lane & 15));
        uint32_t acol = (uint32_t)((lane >> 4) * 16);
        #pragma unroll
        for (int kt = 0; kt < 4; kt++){
            uint32_t off = SWZ(arow*128 + (uint32_t)kt*32 + acol);
            ldsm4(qf[kt], sQ + off);
        }
    }

    float O[8][4];
    #pragma unroll
    for (int i=0;i<8;i++) for (int j=0;j<4;j++) O[i][j]=0.f;
    float mr0 = -INFINITY, mr1 = -INFINITY, l0 = 0.f, l1 = 0.f;

    const float SC = 0.125f * 1.4426950408889634f;
    const uint32_t brow = (uint32_t)((lane & 7) + ((lane >> 4) & 1) * 8);
    const uint32_t bcol = (uint32_t)(((lane >> 3) & 1) * 16);
    const uint32_t vrow = (uint32_t)((lane & 7) + ((lane >> 3) & 1) * 8);
    const uint32_t vcol = (uint32_t)((lane >> 4) * 16);

    for (int jt = 0; jt < nj; jt++){
        const int st = jt & 1, j0 = jt << 7;
        const uint32_t kb = sb + 16384 + (uint32_t)st * 16384;
        const uint32_t vb = sb + 49152 + (uint32_t)st * 16384;

        float S[16][4];
        #pragma unroll
        for (int i=0;i<16;i++) for (int j=0;j<4;j++) S[i][j]=0.f;
        #pragma unroll
        for (int kt = 0; kt < 4; kt++){
            const uint32_t kb2 = (uint32_t)kt * 32;
            #pragma unroll
            for (int g = 0; g < 8; g++){
                uint32_t off = SWZ((brow + g*16)*128 + kb2 + bcol);
                uint32_t kf[4];
                ldsm4(kf, kb + off);
                mma16h(S[g*2    ], qf[kt], kf[0], kf[1]);
                mma16h(S[g*2 + 1], qf[kt], kf[2], kf[3]);
            }
        }

        {
            int gi = i0 + w*16 + (lane >> 2);
            int gjb = j0 + (lane & 3) * 2;
            const float* b0 = bias2 + (size_t)gi * T_ + gjb;
            const float* b1 = bias2 + (size_t)(gi + 8) * T_ + gjb;
            #pragma unroll
            for (int nt = 0; nt < 16; nt++){
                float2 ba = *reinterpret_cast<const float2*>(b0 + nt*8);
                float2 bb = *reinterpret_cast<const float2*>(b1 + nt*8);
                S[nt][0] = S[nt][0]*SC + ba.x;
                S[nt][1] = S[nt][1]*SC + ba.y;
                S[nt][2] = S[nt][2]*SC + bb.x;
                S[nt][3] = S[nt][3]*SC + bb.y;
            }
        }

        float mn0 = mr0, mn1 = mr1;
        #pragma unroll
        for (int nt = 0; nt < 16; nt++){
            mn0 = fmaxf(mn0, fmaxf(S[nt][0], S[nt][1]));
            mn1 = fmaxf(mn1, fmaxf(S[nt][2], S[nt][3]));
        }
        mn0 = fmaxf(mn0, __shfl_xor_sync(0xffffffffu, mn0, 1));
        mn0 = fmaxf(mn0, __shfl_xor_sync(0xffffffffu, mn0, 2));
        mn1 = fmaxf(mn1, __shfl_xor_sync(0xffffffffu, mn1, 1));
        mn1 = fmaxf(mn1, __shfl_xor_sync(0xffffffffu, mn1, 2));
        float sc0 = exp2a(mr0 - mn0), sc1 = exp2a(mr1 - mn1);
        mr0 = mn0; mr1 = mn1;
        float rs0 = 0.f, rs1 = 0.f;
        #pragma unroll
        for (int nt = 0; nt < 16; nt++){
            S[nt][0] = exp2a(S[nt][0] - mn0);
            S[nt][1] = exp2a(S[nt][1] - mn0);
            S[nt][2] = exp2a(S[nt][2] - mn1);
            S[nt][3] = exp2a(S[nt][3] - mn1);
            rs0 += S[nt][0] + S[nt][1];
            rs1 += S[nt][2] + S[nt][3];
        }
        rs0 += __shfl_xor_sync(0xffffffffu, rs0, 1);
        rs0 += __shfl_xor_sync(0xffffffffu, rs0, 2);
        rs1 += __shfl_xor_sync(0xffffffffu, rs1, 1);
        rs1 += __shfl_xor_sync(0xffffffffu, rs1, 2);
        l0 = l0 * sc0 + rs0;
        l1 = l1 * sc1 + rs1;
        #pragma unroll
        for (int nt = 0; nt < 8; nt++){
            O[nt][0] *= sc0; O[nt][1] *= sc0;
            O[nt][2] *= sc1; O[nt][3] *= sc1;
        }

        #pragma unroll
        for (int g = 0; g < 8; g++){
            uint32_t pa[4];
            pa[0] = packh2(S[2*g  ][0], S[2*g  ][1]);
            pa[1] = packh2(S[2*g  ][2], S[2*g  ][3]);
            pa[2] = packh2(S[2*g+1][0], S[2*g+1][1]);
            pa[3] = packh2(S[2*g+1][2], S[2*g+1][3]);
            #pragma unroll
            for (int dv = 0; dv < 4; dv++){
                uint32_t off = SWZ((vrow + g*16)*128 + (uint32_t)dv*32 + vcol);
                uint32_t vf[4];
                ldsm4t(vf, vb + off);
                mma16h(O[dv*2    ], pa, vf[0], vf[1]);
                mma16h(O[dv*2 + 1], pa, vf[2], vf[3]);
            }
        }

        __syncthreads();
        if (jt + 2 < nj) cp_kv(jt + 2);
        if (jt + 1 < nj){
            if (jt + 2 < nj) asm volatile("cp.async.wait_group 1;":::"memory");
            else             asm volatile("cp.async.wait_group 0;":::"memory");
            __syncthreads();
        }
    }

    float li0 = 1.f / l0, li1 = 1.f / l1;
    int r0 = i0 + w*16 + (lane >> 2);
    size_t base0 = (size_t)b * T_ * C_ + (size_t)r0 * C_ + h * D_;
    size_t base1 = base0 + (size_t)8 * C_;
    #pragma unroll
    for (int nt = 0; nt < 8; nt++){
        int col = nt*8 + (lane & 3)*2;
        *reinterpret_cast<uint32_t*>(y + base0 + col) = packh2(O[nt][0]*li0, O[nt][1]*li0);
        *reinterpret_cast<uint32_t*>(y + base1 + col) = packh2(O[nt][2]*li1, O[nt][3]*li1);
    }
}

// ---------------------------------------------------------------------------
// Weight prep: transpose [K,N]->[N,K], single fp16 plane
// ---------------------------------------------------------------------------
__global__ void wtrans16_kernel(const float* __restrict__ in,
                                __half* __restrict__ oh, int K, int N){
    __shared__ float t[32][33];
    size_t lb = (size_t)blockIdx.z * K * N;
    const float* inp = in + lb;
    int kb = blockIdx.y*32, nb = blockIdx.x*32;
    int tx = threadIdx.x, ty = threadIdx.y;
    #pragma unroll
    for (int j = 0; j < 4; j++)
        t[ty + 8*j][tx] = inp[(size_t)(kb + ty + 8*j) * N + nb + tx];
    __syncthreads();
    #pragma unroll
    for (int j = 0; j < 4; j++){
        int n = nb + ty + 8*j, k = kb + tx;
        oh[lb + (size_t)n * K + k] = __float2half_rn(t[tx][ty + 8*j]);
    }
}

// fp16 hi/lo split for wte (already [N,K]) — vectorized: float4 in, uint2 out
__global__ void split_f16_kernel(const float4* __restrict__ in,
                                 uint2* __restrict__ ohi, uint2* __restrict__ olo, int n4){
    int i = blockIdx.x * 256 + threadIdx.x;
    if (i < n4){
        float4 v = in[i];
        __half h0 = __float2half_rn(v.x), h1 = __float2half_rn(v.y);
        __half h2 = __float2half_rn(v.z), h3 = __float2half_rn(v.w);
        __half l0 = __float2half_rn(v.x - __half2float(h0));
        __half l1 = __float2half_rn(v.y - __half2float(h1));
        __half l2 = __float2half_rn(v.z - __half2float(h2));
        __half l3 = __float2half_rn(v.w - __half2float(h3));
        uint2 ho, lo;
        __half2 p01 = __halves2half2(h0, h1), p23 = __halves2half2(h2, h3);
        __half2 q01 = __halves2half2(l0, l1), q23 = __halves2half2(l2, l3);
        ho.x = *reinterpret_cast<uint32_t*>(&p01); ho.y = *reinterpret_cast<uint32_t*>(&p23);
        lo.x = *reinterpret_cast<uint32_t*>(&q01); lo.y = *reinterpret_cast<uint32_t*>(&q23);
        ohi[i] = ho; olo[i] = lo;
    }
}

// ---------------------------------------------------------------------------
// FIRE bias (pre-scaled by log2e)
// ---------------------------------------------------------------------------
__global__ void fire_bias_kernel(const float* __restrict__ log_c,
                                 const float* __restrict__ v1w, const float* __restrict__ v1b,
                                 const float* __restrict__ v2w, const float* __restrict__ v2b,
                                 const float* __restrict__ v3w, const float* __restrict__ v3b,
                                 float* __restrict__ bias) {
    __shared__ float s1w[32], s1b[32], s2w[1024], s2b[32], s3w[32];
    __shared__ float s3b, sc;
    int tid = threadIdx.x;
    if (tid < 32) { s1w[tid] = v1w[tid]; s1b[tid] = v1b[tid]; s2b[tid] = v2b[tid]; s3w[tid] = v3w[tid]; }
    for (int i = tid; i < 1024; i += blockDim.x) s2w[i] = v2w[i];
    if (tid == 0) { s3b = v3b[0]; sc = expf(log_c[0]); }
    __syncthreads();

    int idx = blockIdx.x * blockDim.x + tid;
    if (idx >= T_*T_) return;
    int i = idx / T_, j = idx % T_;
    if (j > i) { bias[idx] = -1e30f; return; }

    float c = sc;
    float fi = (float)(i + 1), fj = (float)(j + 1);
    float pv = logf(c * (fi - fj) + 1.0f) / logf(c * fi + 1.0f);

    float h1[32];
    #pragma unroll
    for (int k = 0; k < 32; k++) h1[k] = fmaxf(pv * s1w[k] + s1b[k], 0.f);
    float out = s3b;
    #pragma unroll
    for (int k2 = 0; k2 < 32; k2++) {
        float a = s2b[k2];
        #pragma unroll
        for (int k1 = 0; k1 < 32; k1++) a += h1[k1] * s2w[k1*32 + k2];
        out += fmaxf(a, 0.f) * s3w[k2];
    }
    bias[idx] = out * 1.4426950408889634f;
}

// ---------------------------------------------------------------------------
// Embedding gather (float4)
// ---------------------------------------------------------------------------
__global__ void embed_kernel(const int* __restrict__ idx, const float* __restrict__ wte,
                             float* __restrict__ x) {
    int row = blockIdx.x;
    const float4* src = reinterpret_cast<const float4*>(wte + (size_t)idx[row] * C_);
    float4* dst = reinterpret_cast<float4*>(x + (size_t)row * C_);
    if (threadIdx.x < 192) dst[threadIdx.x] = src[threadIdx.x];
}

// ---------------------------------------------------------------------------
// LayerNorm: warp-per-row -> fp16 plane
// ---------------------------------------------------------------------------
__global__ void __launch_bounds__(256) ln_kernel(
    const float* __restrict__ x, const float* __restrict__ g,
    const float* __restrict__ b, __half* __restrict__ oh) {
    const int wid = threadIdx.x >> 5, lane = threadIdx.x & 31;
    const int row = blockIdx.x * 8 + wid;
    const float4* xr = reinterpret_cast<const float4*>(x + (size_t)row * C_);
    const float4* g4 = reinterpret_cast<const float4*>(g);
    const float4* b4 = reinterpret_cast<const float4*>(b);

    float4 v[6];
    float s = 0.f;
    #pragma unroll
    for (int c = 0; c < 6; c++){
        v[c] = xr[lane + c*32];
        s += v[c].x + v[c].y + v[c].z + v[c].w;
    }
    #pragma unroll
    for (int o = 16; o > 0; o >>= 1) s += __shfl_xor_sync(0xffffffffu, s, o);
    const float mean = s * (1.0f / C_);

    float q = 0.f;
    #pragma unroll
    for (int c = 0; c < 6; c++){
        v[c].x -= mean; v[c].y -= mean; v[c].z -= mean; v[c].w -= mean;
        q += v[c].x*v[c].x + v[c].y*v[c].y + v[c].z*v[c].z + v[c].w*v[c].w;
    }
    #pragma unroll
    for (int o = 16; o > 0; o >>= 1) q += __shfl_xor_sync(0xffffffffu, q, o);
    const float rs = rsqrtf(q * (1.0f / C_) + 1e-5f);

    const size_t base = (size_t)row * C_;
    #pragma unroll
    for (int c = 0; c < 6; c++){
        int c4 = lane + c*32;
        float4 gg = g4[c4], bb = b4[c4];
        uint2 hh;
        hh.x = packh2(v[c].x*rs*gg.x + bb.x, v[c].y*rs*gg.y + bb.y);
        hh.y = packh2(v[c].z*rs*gg.z + bb.z, v[c].w*rs*gg.w + bb.w);
        *reinterpret_cast<uint2*>(oh + base + c4*4) = hh;
    }
}

// ---------------------------------------------------------------------------
// Launch
// ---------------------------------------------------------------------------
extern "C" void kernel_launch(void* const* d_in, const int* in_sizes, int n_in,
                              void* d_out, int out_size) {
    int o = (n_in >= 2 && in_sizes[1] == 1) ? 1 : 0;

    const int*   idx   = (const int*)  d_in[0];
    const float* wte   = (const float*)d_in[1 + o];
    const float* log_c = (const float*)d_in[2 + o];
    const float* v1w   = (const float*)d_in[3 + o];
    const float* v1b   = (const float*)d_in[4 + o];
    const float* v2w   = (const float*)d_in[5 + o];
    const float* v2b   = (const float*)d_in[6 + o];
    const float* v3w   = (const float*)d_in[7 + o];
    const float* v3b   = (const float*)d_in[8 + o];
    const float* ln1g  = (const float*)d_in[9 + o];
    const float* ln1b  = (const float*)d_in[10 + o];
    const float* attnw = (const float*)d_in[11 + o];
    const float* attnb = (const float*)d_in[12 + o];
    const float* projw = (const float*)d_in[13 + o];
    const float* projb = (const float*)d_in[14 + o];
    const float* ln2g  = (const float*)d_in[15 + o];
    const float* ln2b  = (const float*)d_in[16 + o];
    const float* fcw   = (const float*)d_in[17 + o];
    const float* fcb   = (const float*)d_in[18 + o];
    const float* fc2w  = (const float*)d_in[19 + o];
    const float* fc2b  = (const float*)d_in[20 + o];
    const float* lnfg  = (const float*)d_in[21 + o];
    const float* lnfb  = (const float*)d_in[22 + o];

    float *bias, *x;
    __half *h16, *qkv16, *y16, *mlp16;
    __half *wa, *wp, *wf, *wf2, *wteh, *wtel;
    cudaGetSymbolAddress((void**)&bias,  g_bias);
    cudaGetSymbolAddress((void**)&x,     g_x);
    cudaGetSymbolAddress((void**)&h16,   g_h16);
    cudaGetSymbolAddress((void**)&qkv16, g_qkv16);
    cudaGetSymbolAddress((void**)&y16,   g_y16);
    cudaGetSymbolAddress((void**)&mlp16, g_mlp16);
    cudaGetSymbolAddress((void**)&wa,    g_wa);
    cudaGetSymbolAddress((void**)&wp,    g_wp);
    cudaGetSymbolAddress((void**)&wf,    g_wf);
    cudaGetSymbolAddress((void**)&wf2,   g_wf2);
    cudaGetSymbolAddress((void**)&wteh,  g_wteh);
    cudaGetSymbolAddress((void**)&wtel,  g_wtel);

    // smem sizes (R13-validated configs)
    const int SMQ = 3*24576 + 1024;   // BN128, WPROD1, 3 stages -> 3 CTAs/SM
    const int SMP = 3*16384 + 1024;   // BN64,  WPROD1, 3 stages -> 4 CTAs/SM
    const int SML = 2*40960 + 1024;   // BN128, WPROD2, 2 stages -> 2 CTAs/SM

    cudaFuncSetAttribute(mma_gemm<0,true ,1,3,128>, cudaFuncAttributeMaxDynamicSharedMemorySize, SMQ);
    cudaFuncSetAttribute(mma_gemm<1,true ,1,3,128>, cudaFuncAttributeMaxDynamicSharedMemorySize, SMQ);
    cudaFuncSetAttribute(mma_gemm<0,false,1,3, 64>, cudaFuncAttributeMaxDynamicSharedMemorySize, SMP);
    cudaFuncSetAttribute(mma_gemm<0,false,2,2,128>, cudaFuncAttributeMaxDynamicSharedMemorySize, SML);
    cudaFuncSetAttribute(flash_kernel,              cudaFuncAttributeMaxDynamicSharedMemorySize, FLASH_SMEM);

    // 1. FIRE bias + embedding + weight prep
    fire_bias_kernel<<<(T_*T_ + 255) / 256, 256>>>(log_c, v1w, v1b, v2w, v2b, v3w, v3b, bias);
    embed_kernel<<<M_, 192>>>(idx, wte, x);
    {
        dim3 tb(32, 8);
        wtrans16_kernel<<<dim3(3*C_/32,  C_/32,  L_), tb>>>(attnw, wa,  C_,   3*C_);
        wtrans16_kernel<<<dim3(C_/32,    C_/32,  L_), tb>>>(projw, wp,  C_,   C_);
        wtrans16_kernel<<<dim3(4*C_/32,  C_/32,  L_), tb>>>(fcw,   wf,  C_,   4*C_);
        wtrans16_kernel<<<dim3(C_/32,  4*C_/32,  L_), tb>>>(fc2w,  wf2, 4*C_, C_);
        // V*C = 50257*768 is divisible by 4
        split_f16_kernel<<<((V_*C_/4) + 255)/256, 256>>>(
            (const float4*)wte, (uint2*)wteh, (uint2*)wtel, V_*C_/4);
    }

    // 2. Transformer layers
    const dim3 g_qkvd(M_/64, 3*C_/128);
    const dim3 g_cc  (M_/64, C_/64);
    const dim3 g_fc  (M_/64, 4*C_/128);
    const dim3 g_fl  (T_/128, B_*H_);

    for (int l = 0; l < L_; l++) {
        size_t wao = (size_t)l*3*C_*C_, wpo = (size_t)l*C_*C_, wfo = (size_t)l*4*C_*C_;
        ln_kernel<<<M_/8, 256>>>(x, ln1g + (size_t)l*C_, ln1b + (size_t)l*C_, h16);
        mma_gemm<0,true,1,3,128><<<g_qkvd, 128, SMQ>>>(h16, wa + wao, nullptr,
                                                       attnb + (size_t)l*3*C_, nullptr,
                                                       nullptr, qkv16, 3*C_, C_);
        flash_kernel<<<g_fl, 256, FLASH_SMEM>>>(qkv16, bias, y16);
        mma_gemm<0,false,1,3,64><<<g_cc, 128, SMP>>>(y16, wp + wpo, nullptr,
                                                     projb + (size_t)l*C_, x,
                                                     x, nullptr, C_, C_);
        ln_kernel<<<M_/8, 256>>>(x, ln2g + (size_t)l*C_, ln2b + (size_t)l*C_, h16);
        mma_gemm<1,true,1,3,128><<<g_fc, 128, SMQ>>>(h16, wf + wfo, nullptr,
                                                     fcb + (size_t)l*4*C_, nullptr,
                                                     nullptr, mlp16, 4*C_, C_);
        mma_gemm<0,false,1,3,64><<<g_cc, 128, SMP>>>(mlp16, wf2 + wfo, nullptr,
                                                     fc2b + (size_t)l*C_, x,
                                                     x, nullptr, C_, 4*C_);
    }

    // 3. Final LN + tied LM head (fp16 2-product)
    ln_kernel<<<M_/8, 256>>>(x, lnfg, lnfb, h16);
    const dim3 g_lm(M_/64, (V_ + 127)/128);
    mma_gemm<0,false,2,2,128><<<g_lm, 128, SML>>>(h16, wteh, wtel,
                                                  nullptr, nullptr,
                                                  (float*)d_out, nullptr, V_, C_);
}

// round 17
// speedup vs baseline: 1.0850x; 1.0409x over previous
#include <cuda_runtime.h>
#include <cuda_bf16.h>
#include <cuda_fp16.h>
#include <math.h>
#include <stdint.h>

// Problem constants
#define L_ 12
#define H_ 12
#define C_ 768
#define V_ 50257
#define B_ 2
#define T_ 1024
#define D_ 64
#define M_ (B_*T_)   // 2048 rows

// ---------------------------------------------------------------------------
// Scratch (static device globals) — all-fp16 pipeline
// ---------------------------------------------------------------------------
__device__ float g_bias[T_*T_];
__device__ float g_x   [M_*C_];

__device__ __half g_h16 [M_*C_];
__device__ __half g_qkv16[M_*3*C_];
__device__ __half g_y16 [M_*C_];
__device__ __half g_mlp16[M_*4*C_];

// Layer weights: single fp16 plane (1-product)
__device__ __half g_wa  [L_*3*C_*C_];
__device__ __half g_wp  [L_*C_*C_];
__device__ __half g_wf  [L_*4*C_*C_];
__device__ __half g_wf2 [L_*C_*4*C_];
// LM head: fp16 hi/lo (2-product)
__device__ __half g_wteh[(size_t)V_*C_], g_wtel[(size_t)V_*C_];

// ---------------------------------------------------------------------------
// Helpers
// ---------------------------------------------------------------------------
__device__ __forceinline__ uint32_t smem_u32(const void* p){
    uint32_t a;
    asm("{ .reg .u64 t; cvta.to.shared.u64 t, %1; cvt.u32.u64 %0, t; }":"=r"(a):"l"(p));
    return a;
}
__device__ __forceinline__ void cpa16(uint32_t saddr, const void* gptr){
    asm volatile("cp.async.cg.shared.global [%0], [%1], 16;"::"r"(saddr),"l"(gptr));
}
__device__ __forceinline__ void cpa16z(uint32_t saddr, const void* gptr, int ssz){
    asm volatile("cp.async.cg.shared.global [%0], [%1], 16, %2;"::"r"(saddr),"l"(gptr),"r"(ssz));
}
__device__ __forceinline__ void ldsm4(uint32_t* r, uint32_t addr){
    asm volatile("ldmatrix.sync.aligned.m8n8.x4.shared.b16 {%0,%1,%2,%3}, [%4];"
      : "=r"(r[0]),"=r"(r[1]),"=r"(r[2]),"=r"(r[3]) : "r"(addr));
}
__device__ __forceinline__ void ldsm4t(uint32_t* r, uint32_t addr){
    asm volatile("ldmatrix.sync.aligned.m8n8.x4.trans.shared.b16 {%0,%1,%2,%3}, [%4];"
      : "=r"(r[0]),"=r"(r[1]),"=r"(r[2]),"=r"(r[3]) : "r"(addr));
}
__device__ __forceinline__ void mma16h(float* d, const uint32_t* a, uint32_t b0, uint32_t b1){
    asm volatile("mma.sync.aligned.m16n8k16.row.col.f32.f16.f16.f32 "
      "{%0,%1,%2,%3}, {%4,%5,%6,%7}, {%8,%9}, {%0,%1,%2,%3};"
      : "+f"(d[0]),"+f"(d[1]),"+f"(d[2]),"+f"(d[3])
      : "r"(a[0]),"r"(a[1]),"r"(a[2]),"r"(a[3]),"r"(b0),"r"(b1));
}
__device__ __forceinline__ float exp2a(float x){
    float y; asm("ex2.approx.ftz.f32 %0, %1;":"=f"(y):"f"(x)); return y;
}
__device__ __forceinline__ float rcpa(float x){
    float y; asm("rcp.approx.ftz.f32 %0, %1;":"=f"(y):"f"(x)); return y;
}
__device__ __forceinline__ float gelu_f(float v){
    float u = 0.7978845608028654f*(v + 0.044715f*v*v*v);
    float t = exp2a(u * 2.8853900817779268f);
    return v - v * rcpa(t + 1.0f);
}
__device__ __forceinline__ uint32_t packh2(float c0, float c1){
    uint32_t r; asm("cvt.rn.f16x2.f32 %0, %1, %2;" : "=r"(r) : "f"(c1), "f"(c0));
    return r;
}
#define SWZ(o) ((o) ^ (((o)>>3)&0x70))

// ---------------------------------------------------------------------------
// FP16 GEMM: C = act(A @ B^T + bias) (+resid)
//   A: [M,K] fp16. B: [N,K] fp16 (WPROD=2 adds lo plane).
//   BM=64, 128 threads. BN_ in {128, 64}.
//   Occupancy: BN64 -> 4 CTAs/SM (both WPROD); BN128 WPROD1 -> 3; BN128 WPROD2 -> 2.
//   Grid: bm = blockIdx.x*64 (M fastest), bn = blockIdx.y*BN_.
// ---------------------------------------------------------------------------
template<int ACT, bool OUTH, int WPROD, int NSTAGE, int BN_>
__global__ void __launch_bounds__(128, (BN_==64) ? 4 : ((WPROD==2) ? 2 : 3))
mma_gemm(
    const __half* __restrict__ A,
    const __half* __restrict__ Bh, const __half* __restrict__ Bl,
    const float* __restrict__ bias, const float* __restrict__ resid,
    float* __restrict__ Cf, __half* __restrict__ Ch,
    int Nn, int Kk)
{
    constexpr uint32_t ABYTES = 8192;                 // 64 rows x 128B
    constexpr uint32_t BPLANE = (uint32_t)BN_ * 128;  // per B plane
    constexpr uint32_t BBYTES = (WPROD==2) ? 2*BPLANE : BPLANE;
    constexpr uint32_t STAGE  = ABYTES + BBYTES;
    constexpr int NBIT  = (BN_*8)/128;                // B cp iterations
    constexpr int NHALF = BN_/2;                      // cols per warp
    constexpr int NGRP  = NHALF/16;                   // 16-col ldsm groups/warp

    extern __shared__ char ds[];
    const uint32_t sb = (smem_u32(ds) + 1023) & ~1023u;

    const int tid = threadIdx.x, lane = tid & 31, wid = tid >> 5;
    const int bm = blockIdx.x * 64, bn = blockIdx.y * BN_;
    const int NT = Kk >> 6;

    auto cp_stage = [&](int t){
        const uint32_t base = sb + (uint32_t)(t % NSTAGE) * STAGE;
        const int k0 = t << 6;
        #pragma unroll
        for (int i = 0; i < 4; i++){
            int idx = tid + i*128;
            int r = idx >> 3, c = idx & 7;
            uint32_t off = SWZ((uint32_t)(r*128 + c*16));
            cpa16(base + off, A + (size_t)(bm + r) * Kk + k0 + c*8);
        }
        #pragma unroll
        for (int i = 0; i < NBIT; i++){
            int idx = tid + i*128;
            int r = idx >> 3, c = idx & 7;
            uint32_t off = SWZ((uint32_t)(r*128 + c*16));
            int gn = bn + r;
            size_t kb = (size_t)gn * Kk + k0 + c*8;
            int ssz = (gn < Nn) ? 16 : 0;
            cpa16z(base + ABYTES + off, Bh + kb, ssz);
            if (WPROD == 2) cpa16z(base + ABYTES + BPLANE + off, Bl + kb, ssz);
        }
        asm volatile("cp.async.commit_group;":::"memory");
    };

    float acc[2][NGRP*2][4];
    #pragma unroll
    for (int a=0;a<2;a++) for (int b=0;b<NGRP*2;b++) for (int c=0;c<4;c++) acc[a][b][c]=0.f;

    const int m0 = (wid >> 1) * 32, n0 = (wid & 1) * NHALF;
    const uint32_t arow = (uint32_t)(m0 + (lane & 15));
    const uint32_t acol = (uint32_t)((lane >> 4) * 16);
    const uint32_t brow = (uint32_t)(n0 + (lane & 7) + ((lane >> 4) & 1) * 8);
    const uint32_t bcol = (uint32_t)(((lane >> 3) & 1) * 16);

    auto compute = [&](int t){
        const uint32_t base = sb + (uint32_t)(t % NSTAGE) * STAGE;
        #pragma unroll
        for (int ks = 0; ks < 4; ks++){
            const uint32_t kb2 = (uint32_t)(ks * 32);
            uint32_t ah[2][4];
            #pragma unroll
            for (int mt = 0; mt < 2; mt++){
                uint32_t off = SWZ((arow + mt*16)*128 + kb2 + acol);
                ldsm4(ah[mt], base + off);
            }
            #pragma unroll
            for (int g = 0; g < NGRP; g++){
                uint32_t off = SWZ((brow + g*16)*128 + kb2 + bcol);
                uint32_t bh[4], bl[4];
                ldsm4(bh, base + ABYTES + off);
                if (WPROD == 2) ldsm4(bl, base + ABYTES + BPLANE + off);
                #pragma unroll
                for (int mt = 0; mt < 2; mt++){
                    #pragma unroll
                    for (int sub = 0; sub < 2; sub++){
                        float* d = acc[mt][g*2 + sub];
                        mma16h(d, ah[mt], bh[sub*2], bh[sub*2+1]);
                        if (WPROD == 2) mma16h(d, ah[mt], bl[sub*2], bl[sub*2+1]);
                    }
                }
            }
        }
    };

    cp_stage(0);
    if (NT > 1) cp_stage(1);
    for (int t = 0; t < NT; t++){
        if (t + 1 < NT) asm volatile("cp.async.wait_group 1;":::"memory");
        else            asm volatile("cp.async.wait_group 0;":::"memory");
        __syncthreads();
        compute(t);
        if (NSTAGE == 2) __syncthreads();
        if (t + 2 < NT) cp_stage(t + 2);
    }

    #pragma unroll
    for (int mt = 0; mt < 2; mt++){
        #pragma unroll
        for (int h2 = 0; h2 < 2; h2++){
            int row = bm + m0 + mt*16 + (lane>>2) + h2*8;
            float* crow = OUTH ? nullptr : (Cf + (size_t)row * Nn);
            const float* rrow = resid ? resid + (size_t)row * Nn : nullptr;
            #pragma unroll
            for (int nt = 0; nt < NGRP*2; nt++){
                int col = bn + n0 + nt*8 + (lane&3)*2;
                if (col >= Nn) continue;
                float v0 = acc[mt][nt][h2*2+0];
                float v1 = acc[mt][nt][h2*2+1];
                bool has1 = (col + 1 < Nn);
                if (bias){ v0 += bias[col]; if (has1) v1 += bias[col+1]; }
                if (ACT == 1){ v0 = gelu_f(v0); v1 = gelu_f(v1); }
                if (rrow){ v0 += rrow[col]; if (has1) v1 += rrow[col+1]; }
                if (OUTH){
                    *reinterpret_cast<uint32_t*>(Ch + (size_t)row * Nn + col) = packh2(v0, v1);
                } else if (((Nn & 1) == 0) && has1){
                    float2 st; st.x = v0; st.y = v1;
                    *reinterpret_cast<float2*>(crow + col) = st;
                } else {
                    crow[col] = v0;
                    if (has1) crow[col + 1] = v1;
                }
            }
        }
    }
}

// ---------------------------------------------------------------------------
// FlashAttention, plain fp16 (R13 configuration).
// smem: Q 16K | K 2st 32K | V 2st 32K = 80K -> 2 CTAs/SM.
// ---------------------------------------------------------------------------
#define FLASH_SMEM (81920 + 1024)

__global__ void __launch_bounds__(256) flash_kernel(
    const __half* __restrict__ qkv,
    const float* __restrict__ bias2,
    __half* __restrict__ y)
{
    extern __shared__ char ds[];
    const uint32_t sb = (smem_u32(ds) + 1023) & ~1023u;
    const uint32_t sQ = sb;

    const int tid = threadIdx.x, lane = tid & 31, w = tid >> 5;
    const int bh = blockIdx.y, b = bh / H_, h = bh % H_;
    const int i0 = (int)(gridDim.x - 1 - blockIdx.x) * 128;
    const int nj = (i0 >> 7) + 1;

    const __half* qp = qkv + (size_t)b * T_ * 3 * C_ + h * D_;
    const __half* kp = qp + C_;
    const __half* vp = qp + 2*C_;

    auto cp_q = [&](){
        #pragma unroll
        for (int i = 0; i < 4; i++){
            int idx = tid + i*256;
            int r = idx >> 3, c = idx & 7;
            uint32_t off = SWZ((uint32_t)(r*128 + c*16));
            cpa16(sQ + off, qp + (size_t)(i0 + r) * 3 * C_ + c*8);
        }
    };
    auto cp_kv = [&](int jt){
        int st = jt & 1, j0 = jt << 7;
        uint32_t kb = sb + 16384 + (uint32_t)st * 16384;
        uint32_t vb = sb + 49152 + (uint32_t)st * 16384;
        #pragma unroll
        for (int i = 0; i < 4; i++){
            int idx = tid + i*256;
            int r = idx >> 3, c = idx & 7;
            uint32_t off = SWZ((uint32_t)(r*128 + c*16));
            size_t g = (size_t)(j0 + r) * 3 * C_ + c*8;
            cpa16(kb + off, kp + g);
            cpa16(vb + off, vp + g);
        }
        asm volatile("cp.async.commit_group;":::"memory");
    };

    cp_q(); cp_kv(0);
    if (nj > 1) cp_kv(1);
    if (nj > 1) asm volatile("cp.async.wait_group 1;":::"memory");
    else        asm volatile("cp.async.wait_group 0;":::"memory");
    __syncthreads();

    uint32_t qf[4][4];
    {
        uint32_t arow = (uint32_t)(w*16 + (lane & 15));
        uint32_t acol = (uint32_t)((lane >> 4) * 16);
        #pragma unroll
        for (int kt = 0; kt < 4; kt++){
            uint32_t off = SWZ(arow*128 + (uint32_t)kt*32 + acol);
            ldsm4(qf[kt], sQ + off);
        }
    }

    float O[8][4];
    #pragma unroll
    for (int i=0;i<8;i++) for (int j=0;j<4;j++) O[i][j]=0.f;
    float mr0 = -INFINITY, mr1 = -INFINITY, l0 = 0.f, l1 = 0.f;

    const float SC = 0.125f * 1.4426950408889634f;
    const uint32_t brow = (uint32_t)((lane & 7) + ((lane >> 4) & 1) * 8);
    const uint32_t bcol = (uint32_t)(((lane >> 3) & 1) * 16);
    const uint32_t vrow = (uint32_t)((lane & 7) + ((lane >> 3) & 1) * 8);
    const uint32_t vcol = (uint32_t)((lane >> 4) * 16);

    for (int jt = 0; jt < nj; jt++){
        const int st = jt & 1, j0 = jt << 7;
        const uint32_t kb = sb + 16384 + (uint32_t)st * 16384;
        const uint32_t vb = sb + 49152 + (uint32_t)st * 16384;

        float S[16][4];
        #pragma unroll
        for (int i=0;i<16;i++) for (int j=0;j<4;j++) S[i][j]=0.f;
        #pragma unroll
        for (int kt = 0; kt < 4; kt++){
            const uint32_t kb2 = (uint32_t)kt * 32;
            #pragma unroll
            for (int g = 0; g < 8; g++){
                uint32_t off = SWZ((brow + g*16)*128 + kb2 + bcol);
                uint32_t kf[4];
                ldsm4(kf, kb + off);
                mma16h(S[g*2    ], qf[kt], kf[0], kf[1]);
                mma16h(S[g*2 + 1], qf[kt], kf[2], kf[3]);
            }
        }

        {
            int gi = i0 + w*16 + (lane >> 2);
            int gjb = j0 + (lane & 3) * 2;
            const float* b0 = bias2 + (size_t)gi * T_ + gjb;
            const float* b1 = bias2 + (size_t)(gi + 8) * T_ + gjb;
            #pragma unroll
            for (int nt = 0; nt < 16; nt++){
                float2 ba = *reinterpret_cast<const float2*>(b0 + nt*8);
                float2 bb = *reinterpret_cast<const float2*>(b1 + nt*8);
                S[nt][0] = S[nt][0]*SC + ba.x;
                S[nt][1] = S[nt][1]*SC + ba.y;
                S[nt][2] = S[nt][2]*SC + bb.x;
                S[nt][3] = S[nt][3]*SC + bb.y;
            }
        }

        float mn0 = mr0, mn1 = mr1;
        #pragma unroll
        for (int nt = 0; nt < 16; nt++){
            mn0 = fmaxf(mn0, fmaxf(S[nt][0], S[nt][1]));
            mn1 = fmaxf(mn1, fmaxf(S[nt][2], S[nt][3]));
        }
        mn0 = fmaxf(mn0, __shfl_xor_sync(0xffffffffu, mn0, 1));
        mn0 = fmaxf(mn0, __shfl_xor_sync(0xffffffffu, mn0, 2));
        mn1 = fmaxf(mn1, __shfl_xor_sync(0xffffffffu, mn1, 1));
        mn1 = fmaxf(mn1, __shfl_xor_sync(0xffffffffu, mn1, 2));
        float sc0 = exp2a(mr0 - mn0), sc1 = exp2a(mr1 - mn1);
        mr0 = mn0; mr1 = mn1;
        float rs0 = 0.f, rs1 = 0.f;
        #pragma unroll
        for (int nt = 0; nt < 16; nt++){
            S[nt][0] = exp2a(S[nt][0] - mn0);
            S[nt][1] = exp2a(S[nt][1] - mn0);
            S[nt][2] = exp2a(S[nt][2] - mn1);
            S[nt][3] = exp2a(S[nt][3] - mn1);
            rs0 += S[nt][0] + S[nt][1];
            rs1 += S[nt][2] + S[nt][3];
        }
        rs0 += __shfl_xor_sync(0xffffffffu, rs0, 1);
        rs0 += __shfl_xor_sync(0xffffffffu, rs0, 2);
        rs1 += __shfl_xor_sync(0xffffffffu, rs1, 1);
        rs1 += __shfl_xor_sync(0xffffffffu, rs1, 2);
        l0 = l0 * sc0 + rs0;
        l1 = l1 * sc1 + rs1;
        #pragma unroll
        for (int nt = 0; nt < 8; nt++){
            O[nt][0] *= sc0; O[nt][1] *= sc0;
            O[nt][2] *= sc1; O[nt][3] *= sc1;
        }

        #pragma unroll
        for (int g = 0; g < 8; g++){
            uint32_t pa[4];
            pa[0] = packh2(S[2*g  ][0], S[2*g  ][1]);
            pa[1] = packh2(S[2*g  ][2], S[2*g  ][3]);
            pa[2] = packh2(S[2*g+1][0], S[2*g+1][1]);
            pa[3] = packh2(S[2*g+1][2], S[2*g+1][3]);
            #pragma unroll
            for (int dv = 0; dv < 4; dv++){
                uint32_t off = SWZ((vrow + g*16)*128 + (uint32_t)dv*32 + vcol);
                uint32_t vf[4];
                ldsm4t(vf, vb + off);
                mma16h(O[dv*2    ], pa, vf[0], vf[1]);
                mma16h(O[dv*2 + 1], pa, vf[2], vf[3]);
            }
        }

        __syncthreads();
        if (jt + 2 < nj) cp_kv(jt + 2);
        if (jt + 1 < nj){
            if (jt + 2 < nj) asm volatile("cp.async.wait_group 1;":::"memory");
            else             asm volatile("cp.async.wait_group 0;":::"memory");
            __syncthreads();
        }
    }

    float li0 = 1.f / l0, li1 = 1.f / l1;
    int r0 = i0 + w*16 + (lane >> 2);
    size_t base0 = (size_t)b * T_ * C_ + (size_t)r0 * C_ + h * D_;
    size_t base1 = base0 + (size_t)8 * C_;
    #pragma unroll
    for (int nt = 0; nt < 8; nt++){
        int col = nt*8 + (lane & 3)*2;
        *reinterpret_cast<uint32_t*>(y + base0 + col) = packh2(O[nt][0]*li0, O[nt][1]*li0);
        *reinterpret_cast<uint32_t*>(y + base1 + col) = packh2(O[nt][2]*li1, O[nt][3]*li1);
    }
}

// ---------------------------------------------------------------------------
// Weight prep: transpose [K,N]->[N,K], single fp16 plane
// ---------------------------------------------------------------------------
__global__ void wtrans16_kernel(const float* __restrict__ in,
                                __half* __restrict__ oh, int K, int N){
    __shared__ float t[32][33];
    size_t lb = (size_t)blockIdx.z * K * N;
    const float* inp = in + lb;
    int kb = blockIdx.y*32, nb = blockIdx.x*32;
    int tx = threadIdx.x, ty = threadIdx.y;
    #pragma unroll
    for (int j = 0; j < 4; j++)
        t[ty + 8*j][tx] = inp[(size_t)(kb + ty + 8*j) * N + nb + tx];
    __syncthreads();
    #pragma unroll
    for (int j = 0; j < 4; j++){
        int n = nb + ty + 8*j, k = kb + tx;
        oh[lb + (size_t)n * K + k] = __float2half_rn(t[tx][ty + 8*j]);
    }
}

// fp16 hi/lo split for wte (already [N,K]) — vectorized: float4 in, uint2 out
__global__ void split_f16_kernel(const float4* __restrict__ in,
                                 uint2* __restrict__ ohi, uint2* __restrict__ olo, int n4){
    int i = blockIdx.x * 256 + threadIdx.x;
    if (i < n4){
        float4 v = in[i];
        __half h0 = __float2half_rn(v.x), h1 = __float2half_rn(v.y);
        __half h2 = __float2half_rn(v.z), h3 = __float2half_rn(v.w);
        __half l0 = __float2half_rn(v.x - __half2float(h0));
        __half l1 = __float2half_rn(v.y - __half2float(h1));
        __half l2 = __float2half_rn(v.z - __half2float(h2));
        __half l3 = __float2half_rn(v.w - __half2float(h3));
        uint2 ho, lo;
        __half2 p01 = __halves2half2(h0, h1), p23 = __halves2half2(h2, h3);
        __half2 q01 = __halves2half2(l0, l1), q23 = __halves2half2(l2, l3);
        ho.x = *reinterpret_cast<uint32_t*>(&p01); ho.y = *reinterpret_cast<uint32_t*>(&p23);
        lo.x = *reinterpret_cast<uint32_t*>(&q01); lo.y = *reinterpret_cast<uint32_t*>(&q23);
        ohi[i] = ho; olo[i] = lo;
    }
}

// ---------------------------------------------------------------------------
// FIRE bias (pre-scaled by log2e)
// ---------------------------------------------------------------------------
__global__ void fire_bias_kernel(const float* __restrict__ log_c,
                                 const float* __restrict__ v1w, const float* __restrict__ v1b,
                                 const float* __restrict__ v2w, const float* __restrict__ v2b,
                                 const float* __restrict__ v3w, const float* __restrict__ v3b,
                                 float* __restrict__ bias) {
    __shared__ float s1w[32], s1b[32], s2w[1024], s2b[32], s3w[32];
    __shared__ float s3b, sc;
    int tid = threadIdx.x;
    if (tid < 32) { s1w[tid] = v1w[tid]; s1b[tid] = v1b[tid]; s2b[tid] = v2b[tid]; s3w[tid] = v3w[tid]; }
    for (int i = tid; i < 1024; i += blockDim.x) s2w[i] = v2w[i];
    if (tid == 0) { s3b = v3b[0]; sc = expf(log_c[0]); }
    __syncthreads();

    int idx = blockIdx.x * blockDim.x + tid;
    if (idx >= T_*T_) return;
    int i = idx / T_, j = idx % T_;
    if (j > i) { bias[idx] = -1e30f; return; }

    float c = sc;
    float fi = (float)(i + 1), fj = (float)(j + 1);
    float pv = logf(c * (fi - fj) + 1.0f) / logf(c * fi + 1.0f);

    float h1[32];
    #pragma unroll
    for (int k = 0; k < 32; k++) h1[k] = fmaxf(pv * s1w[k] + s1b[k], 0.f);
    float out = s3b;
    #pragma unroll
    for (int k2 = 0; k2 < 32; k2++) {
        float a = s2b[k2];
        #pragma unroll
        for (int k1 = 0; k1 < 32; k1++) a += h1[k1] * s2w[k1*32 + k2];
        out += fmaxf(a, 0.f) * s3w[k2];
    }
    bias[idx] = out * 1.4426950408889634f;
}

// ---------------------------------------------------------------------------
// Embedding gather (float4)
// ---------------------------------------------------------------------------
__global__ void embed_kernel(const int* __restrict__ idx, const float* __restrict__ wte,
                             float* __restrict__ x) {
    int row = blockIdx.x;
    const float4* src = reinterpret_cast<const float4*>(wte + (size_t)idx[row] * C_);
    float4* dst = reinterpret_cast<float4*>(x + (size_t)row * C_);
    if (threadIdx.x < 192) dst[threadIdx.x] = src[threadIdx.x];
}

// ---------------------------------------------------------------------------
// LayerNorm: warp-per-row -> fp16 plane
// ---------------------------------------------------------------------------
__global__ void __launch_bounds__(256) ln_kernel(
    const float* __restrict__ x, const float* __restrict__ g,
    const float* __restrict__ b, __half* __restrict__ oh) {
    const int wid = threadIdx.x >> 5, lane = threadIdx.x & 31;
    const int row = blockIdx.x * 8 + wid;
    const float4* xr = reinterpret_cast<const float4*>(x + (size_t)row * C_);
    const float4* g4 = reinterpret_cast<const float4*>(g);
    const float4* b4 = reinterpret_cast<const float4*>(b);

    float4 v[6];
    float s = 0.f;
    #pragma unroll
    for (int c = 0; c < 6; c++){
        v[c] = xr[lane + c*32];
        s += v[c].x + v[c].y + v[c].z + v[c].w;
    }
    #pragma unroll
    for (int o = 16; o > 0; o >>= 1) s += __shfl_xor_sync(0xffffffffu, s, o);
    const float mean = s * (1.0f / C_);

    float q = 0.f;
    #pragma unroll
    for (int c = 0; c < 6; c++){
        v[c].x -= mean; v[c].y -= mean; v[c].z -= mean; v[c].w -= mean;
        q += v[c].x*v[c].x + v[c].y*v[c].y + v[c].z*v[c].z + v[c].w*v[c].w;
    }
    #pragma unroll
    for (int o = 16; o > 0; o >>= 1) q += __shfl_xor_sync(0xffffffffu, q, o);
    const float rs = rsqrtf(q * (1.0f / C_) + 1e-5f);

    const size_t base = (size_t)row * C_;
    #pragma unroll
    for (int c = 0; c < 6; c++){
        int c4 = lane + c*32;
        float4 gg = g4[c4], bb = b4[c4];
        uint2 hh;
        hh.x = packh2(v[c].x*rs*gg.x + bb.x, v[c].y*rs*gg.y + bb.y);
        hh.y = packh2(v[c].z*rs*gg.z + bb.z, v[c].w*rs*gg.w + bb.w);
        *reinterpret_cast<uint2*>(oh + base + c4*4) = hh;
    }
}

// ---------------------------------------------------------------------------
// Launch
// ---------------------------------------------------------------------------
extern "C" void kernel_launch(void* const* d_in, const int* in_sizes, int n_in,
                              void* d_out, int out_size) {
    int o = (n_in >= 2 && in_sizes[1] == 1) ? 1 : 0;

    const int*   idx   = (const int*)  d_in[0];
    const float* wte   = (const float*)d_in[1 + o];
    const float* log_c = (const float*)d_in[2 + o];
    const float* v1w   = (const float*)d_in[3 + o];
    const float* v1b   = (const float*)d_in[4 + o];
    const float* v2w   = (const float*)d_in[5 + o];
    const float* v2b   = (const float*)d_in[6 + o];
    const float* v3w   = (const float*)d_in[7 + o];
    const float* v3b   = (const float*)d_in[8 + o];
    const float* ln1g  = (const float*)d_in[9 + o];
    const float* ln1b  = (const float*)d_in[10 + o];
    const float* attnw = (const float*)d_in[11 + o];
    const float* attnb = (const float*)d_in[12 + o];
    const float* projw = (const float*)d_in[13 + o];
    const float* projb = (const float*)d_in[14 + o];
    const float* ln2g  = (const float*)d_in[15 + o];
    const float* ln2b  = (const float*)d_in[16 + o];
    const float* fcw   = (const float*)d_in[17 + o];
    const float* fcb   = (const float*)d_in[18 + o];
    const float* fc2w  = (const float*)d_in[19 + o];
    const float* fc2b  = (const float*)d_in[20 + o];
    const float* lnfg  = (const float*)d_in[21 + o];
    const float* lnfb  = (const float*)d_in[22 + o];

    float *bias, *x;
    __half *h16, *qkv16, *y16, *mlp16;
    __half *wa, *wp, *wf, *wf2, *wteh, *wtel;
    cudaGetSymbolAddress((void**)&bias,  g_bias);
    cudaGetSymbolAddress((void**)&x,     g_x);
    cudaGetSymbolAddress((void**)&h16,   g_h16);
    cudaGetSymbolAddress((void**)&qkv16, g_qkv16);
    cudaGetSymbolAddress((void**)&y16,   g_y16);
    cudaGetSymbolAddress((void**)&mlp16, g_mlp16);
    cudaGetSymbolAddress((void**)&wa,    g_wa);
    cudaGetSymbolAddress((void**)&wp,    g_wp);
    cudaGetSymbolAddress((void**)&wf,    g_wf);
    cudaGetSymbolAddress((void**)&wf2,   g_wf2);
    cudaGetSymbolAddress((void**)&wteh,  g_wteh);
    cudaGetSymbolAddress((void**)&wtel,  g_wtel);

    // smem sizes
    const int SMQ  = 3*24576 + 1024;  // BN128, WPROD1, 3 stages -> 3 CTAs/SM (fc)
    const int SMP  = 3*16384 + 1024;  // BN64,  WPROD1, 3 stages -> 4 CTAs/SM (qkv/proj/fc2)
    const int SML  = 2*24576 + 1024;  // BN64,  WPROD2, 2 stages -> 4 CTAs/SM (LM)

    cudaFuncSetAttribute(mma_gemm<0,true ,1,3, 64>, cudaFuncAttributeMaxDynamicSharedMemorySize, SMP);
    cudaFuncSetAttribute(mma_gemm<1,true ,1,3,128>, cudaFuncAttributeMaxDynamicSharedMemorySize, SMQ);
    cudaFuncSetAttribute(mma_gemm<0,false,1,3, 64>, cudaFuncAttributeMaxDynamicSharedMemorySize, SMP);
    cudaFuncSetAttribute(mma_gemm<0,false,2,2, 64>, cudaFuncAttributeMaxDynamicSharedMemorySize, SML);
    cudaFuncSetAttribute(flash_kernel,              cudaFuncAttributeMaxDynamicSharedMemorySize, FLASH_SMEM);

    // 1. FIRE bias + embedding + weight prep
    fire_bias_kernel<<<(T_*T_ + 255) / 256, 256>>>(log_c, v1w, v1b, v2w, v2b, v3w, v3b, bias);
    embed_kernel<<<M_, 192>>>(idx, wte, x);
    {
        dim3 tb(32, 8);
        wtrans16_kernel<<<dim3(3*C_/32,  C_/32,  L_), tb>>>(attnw, wa,  C_,   3*C_);
        wtrans16_kernel<<<dim3(C_/32,    C_/32,  L_), tb>>>(projw, wp,  C_,   C_);
        wtrans16_kernel<<<dim3(4*C_/32,  C_/32,  L_), tb>>>(fcw,   wf,  C_,   4*C_);
        wtrans16_kernel<<<dim3(C_/32,  4*C_/32,  L_), tb>>>(fc2w,  wf2, 4*C_, C_);
        split_f16_kernel<<<((V_*C_/4) + 255)/256, 256>>>(
            (const float4*)wte, (uint2*)wteh, (uint2*)wtel, V_*C_/4);
    }

    // 2. Transformer layers
    const dim3 g_qkvd(M_/64, 3*C_/64);    // BN=64: 32x36 -> ~2 full waves at 4 CTAs/SM
    const dim3 g_cc  (M_/64, C_/64);
    const dim3 g_fc  (M_/64, 4*C_/128);
    const dim3 g_fl  (T_/128, B_*H_);

    for (int l = 0; l < L_; l++) {
        size_t wao = (size_t)l*3*C_*C_, wpo = (size_t)l*C_*C_, wfo = (size_t)l*4*C_*C_;
        ln_kernel<<<M_/8, 256>>>(x, ln1g + (size_t)l*C_, ln1b + (size_t)l*C_, h16);
        mma_gemm<0,true,1,3,64><<<g_qkvd, 128, SMP>>>(h16, wa + wao, nullptr,
                                                      attnb + (size_t)l*3*C_, nullptr,
                                                      nullptr, qkv16, 3*C_, C_);
        flash_kernel<<<g_fl, 256, FLASH_SMEM>>>(qkv16, bias, y16);
        mma_gemm<0,false,1,3,64><<<g_cc, 128, SMP>>>(y16, wp + wpo, nullptr,
                                                     projb + (size_t)l*C_, x,
                                                     x, nullptr, C_, C_);
        ln_kernel<<<M_/8, 256>>>(x, ln2g + (size_t)l*C_, ln2b + (size_t)l*C_, h16);
        mma_gemm<1,true,1,3,128><<<g_fc, 128, SMQ>>>(h16, wf + wfo, nullptr,
                                                     fcb + (size_t)l*4*C_, nullptr,
                                                     nullptr, mlp16, 4*C_, C_);
        mma_gemm<0,false,1,3,64><<<g_cc, 128, SMP>>>(mlp16, wf2 + wfo, nullptr,
                                                     fc2b + (size_t)l*C_, x,
                                                     x, nullptr, C_, 4*C_);
    }

    // 3. Final LN + tied LM head (fp16 2-product, BN=64, 4 CTAs/SM)
    ln_kernel<<<M_/8, 256>>>(x, lnfg, lnfb, h16);
    const dim3 g_lm(M_/64, (V_ + 63)/64);
    mma_gemm<0,false,2,2,64><<<g_lm, 128, SML>>>(h16, wteh, wtel,
                                                 nullptr, nullptr,
                                                 (float*)d_out, nullptr, V_, C_);
}